// round 1
// baseline (speedup 1.0000x reference)
#include <cuda_runtime.h>
#include <math.h>

#define DIMC  1024
#define NHEAD 16
#define HDIM  64
#define BQ    2
#define NSEQ  2048
#define ROWS  (BQ*NSEQ)      // 4096
#define QKV_F (3*DIMC)       // 3072

// ---- scratch (no allocations allowed) ----
__device__ float g_qkv [ROWS * QKV_F];             // [B,N,3*C]
__device__ float g_q   [BQ*NHEAD*NSEQ*HDIM];       // [B,H,N,D] rmsnorm+rope+scale
__device__ float g_k   [BQ*NHEAD*NSEQ*HDIM];       // [B,H,N,D] rmsnorm+rope
__device__ float g_attn[ROWS * DIMC];              // [B,N,C]

// ============================================================
// GEMM (NT): C[m,n] = sum_k A[m,k]*B[n,k] (+bias[n])
// A:[M,K] row-major, B:[N,K] row-major. 128x128x8 tile, 8x8/thread.
// M,N multiples of 128; K multiple of 8.
// ============================================================
__global__ __launch_bounds__(256) void gemm_nt(
    const float* __restrict__ A, const float* __restrict__ B,
    const float* __restrict__ bias, float* __restrict__ C,
    int M, int N, int K)
{
    __shared__ __align__(16) float As[8][132];
    __shared__ __align__(16) float Bs[8][132];

    const int tid  = threadIdx.x;
    const int tx   = tid & 15;          // 0..15 -> n
    const int ty   = tid >> 4;          // 0..15 -> m
    const int lrow = tid >> 1;          // 0..127
    const int lcol = (tid & 1) << 2;    // 0 or 4

    const float* Ap = A + (size_t)(blockIdx.y * 128 + lrow) * K + lcol;
    const float* Bp = B + (size_t)(blockIdx.x * 128 + lrow) * K + lcol;

    float acc[8][8];
#pragma unroll
    for (int i = 0; i < 8; i++)
#pragma unroll
        for (int j = 0; j < 8; j++) acc[i][j] = 0.f;

    for (int k0 = 0; k0 < K; k0 += 8) {
        float4 av = *(const float4*)(Ap + k0);
        float4 bv = *(const float4*)(Bp + k0);
        __syncthreads();
        As[lcol + 0][lrow] = av.x; As[lcol + 1][lrow] = av.y;
        As[lcol + 2][lrow] = av.z; As[lcol + 3][lrow] = av.w;
        Bs[lcol + 0][lrow] = bv.x; Bs[lcol + 1][lrow] = bv.y;
        Bs[lcol + 2][lrow] = bv.z; Bs[lcol + 3][lrow] = bv.w;
        __syncthreads();
#pragma unroll
        for (int kk = 0; kk < 8; kk++) {
            float4 a0 = *(const float4*)&As[kk][ty * 8];
            float4 a1 = *(const float4*)&As[kk][ty * 8 + 4];
            float4 b0 = *(const float4*)&Bs[kk][tx * 8];
            float4 b1 = *(const float4*)&Bs[kk][tx * 8 + 4];
            float a[8] = {a0.x,a0.y,a0.z,a0.w,a1.x,a1.y,a1.z,a1.w};
            float b[8] = {b0.x,b0.y,b0.z,b0.w,b1.x,b1.y,b1.z,b1.w};
#pragma unroll
            for (int i = 0; i < 8; i++)
#pragma unroll
                for (int j = 0; j < 8; j++)
                    acc[i][j] = fmaf(a[i], b[j], acc[i][j]);
        }
    }

    const int crow = blockIdx.y * 128 + ty * 8;
    const int ccol = blockIdx.x * 128 + tx * 8;
#pragma unroll
    for (int i = 0; i < 8; i++) {
        float4 v0 = make_float4(acc[i][0], acc[i][1], acc[i][2], acc[i][3]);
        float4 v1 = make_float4(acc[i][4], acc[i][5], acc[i][6], acc[i][7]);
        if (bias) {
            v0.x += bias[ccol+0]; v0.y += bias[ccol+1];
            v0.z += bias[ccol+2]; v0.w += bias[ccol+3];
            v1.x += bias[ccol+4]; v1.y += bias[ccol+5];
            v1.z += bias[ccol+6]; v1.w += bias[ccol+7];
        }
        *(float4*)&C[(size_t)(crow + i) * N + ccol]     = v0;
        *(float4*)&C[(size_t)(crow + i) * N + ccol + 4] = v1;
    }
}

// ============================================================
// RMSNorm + rotary for q and k. One warp per (sel,b,h,n) row.
// Lane L owns the rotary pair (2L, 2L+1). Q additionally scaled by D^-0.5.
// ============================================================
__global__ __launch_bounds__(256) void rms_rot_kernel(
    const float* __restrict__ qkv, const float* __restrict__ pos,
    const float* __restrict__ qw, const float* __restrict__ kw,
    float* __restrict__ qout, float* __restrict__ kout)
{
    int wg   = blockIdx.x * (blockDim.x >> 5) + (threadIdx.x >> 5);
    int lane = threadIdx.x & 31;
    int n   =  wg        & (NSEQ - 1);
    int h   = (wg >> 11) & (NHEAD - 1);
    int b   = (wg >> 15) & 1;
    int sel =  wg >> 16;                     // 0 = q, 1 = k

    const float* src = qkv + (size_t)(b * NSEQ + n) * QKV_F + sel * DIMC + h * HDIM + 2 * lane;
    float2 v = *(const float2*)src;
    float ss = v.x * v.x + v.y * v.y;
#pragma unroll
    for (int o = 16; o; o >>= 1) ss += __shfl_xor_sync(0xffffffffu, ss, o);
    float r = rsqrtf(ss * (1.f / HDIM) + 1e-6f);

    const float* w = sel ? kw : qw;
    float xr = v.x * r * w[2 * lane];
    float xi = v.y * r * w[2 * lane + 1];

    float ang = pos[n * (HDIM / 2) + lane];
    float sn, cs;
    __sincosf(ang, &sn, &cs);
    float orr = xr * cs - xi * sn;
    float oi  = xr * sn + xi * cs;
    if (!sel) { orr *= 0.125f; oi *= 0.125f; }   // fold softmax scale into q

    float* dst = (sel ? kout : qout) +
                 (size_t)((b * NHEAD + h) * NSEQ + n) * HDIM + 2 * lane;
    *(float2*)dst = make_float2(orr, oi);
}

// ============================================================
// Flash attention (fp32, non-causal). 1 query row / thread, 128 rows / CTA,
// 32-key tiles in smem (broadcast LDS.128). V read straight from g_qkv.
// ============================================================
__global__ __launch_bounds__(128) void attn_kernel(
    const float* __restrict__ Q, const float* __restrict__ Kt,
    const float* __restrict__ QKV, float* __restrict__ Out)
{
    __shared__ __align__(16) float ks[32 * HDIM];
    __shared__ __align__(16) float vs[32 * HDIM];

    const int tid = threadIdx.x;
    const int b = blockIdx.z, h = blockIdx.y;
    const int m = blockIdx.x * 128 + tid;

    const float* qrow = Q + ((size_t)((b * NHEAD + h) * NSEQ) + m) * HDIM;
    float4 q4[16];
#pragma unroll
    for (int i = 0; i < 16; i++) q4[i] = *(const float4*)(qrow + i * 4);

    float4 o4[16];
#pragma unroll
    for (int i = 0; i < 16; i++) o4[i] = make_float4(0.f, 0.f, 0.f, 0.f);
    float mval = -1e30f, l = 0.f;

    const float* kbase = Kt + (size_t)((b * NHEAD + h) * NSEQ) * HDIM;
    const float* vbase = QKV + (size_t)b * NSEQ * QKV_F + 2 * DIMC + h * HDIM;

    for (int j0 = 0; j0 < NSEQ; j0 += 32) {
        // K tile: 32 rows x 64 = 2048 contiguous floats
        const float4* ksrc = (const float4*)(kbase + (size_t)j0 * HDIM);
#pragma unroll
        for (int i = 0; i < 4; i++) ((float4*)ks)[tid + i * 128] = ksrc[tid + i * 128];
        // V tile: rows strided by 3072 in g_qkv
#pragma unroll
        for (int i = 0; i < 4; i++) {
            int f = tid + i * 128;            // float4 index 0..511
            int r = f >> 4, c = f & 15;
            ((float4*)vs)[f] = *(const float4*)(vbase + (size_t)(j0 + r) * QKV_F + c * 4);
        }
        __syncthreads();

        float s[32];
#pragma unroll
        for (int j = 0; j < 32; j++) {
            const float4* kr4 = (const float4*)(ks + j * HDIM);
            float acc = 0.f;
#pragma unroll
            for (int i = 0; i < 16; i++) {
                float4 kv = kr4[i];
                acc = fmaf(q4[i].x, kv.x, acc);
                acc = fmaf(q4[i].y, kv.y, acc);
                acc = fmaf(q4[i].z, kv.z, acc);
                acc = fmaf(q4[i].w, kv.w, acc);
            }
            s[j] = acc;
        }

        float tmax = mval;
#pragma unroll
        for (int j = 0; j < 32; j++) tmax = fmaxf(tmax, s[j]);
        float corr = __expf(mval - tmax);
        mval = tmax;
        l *= corr;
#pragma unroll
        for (int i = 0; i < 16; i++) {
            o4[i].x *= corr; o4[i].y *= corr; o4[i].z *= corr; o4[i].w *= corr;
        }
#pragma unroll
        for (int j = 0; j < 32; j++) {
            float p = __expf(s[j] - mval);
            l += p;
            const float4* vr4 = (const float4*)(vs + j * HDIM);
#pragma unroll
            for (int i = 0; i < 16; i++) {
                float4 vv = vr4[i];
                o4[i].x = fmaf(p, vv.x, o4[i].x);
                o4[i].y = fmaf(p, vv.y, o4[i].y);
                o4[i].z = fmaf(p, vv.z, o4[i].z);
                o4[i].w = fmaf(p, vv.w, o4[i].w);
            }
        }
        __syncthreads();
    }

    float inv = 1.f / l;
    float* dst = Out + (size_t)(b * NSEQ + m) * DIMC + h * HDIM;
#pragma unroll
    for (int i = 0; i < 16; i++) {
        float4 v = o4[i];
        v.x *= inv; v.y *= inv; v.z *= inv; v.w *= inv;
        *(float4*)(dst + i * 4) = v;
    }
}

// ============================================================
extern "C" void kernel_launch(void* const* d_in, const int* in_sizes, int n_in,
                              void* d_out, int out_size)
{
    const float* x      = (const float*)d_in[0];
    const float* pos    = (const float*)d_in[1];
    const float* qkv_w  = (const float*)d_in[2];
    const float* qnw    = (const float*)d_in[3];
    const float* knw    = (const float*)d_in[4];
    const float* proj_w = (const float*)d_in[5];
    const float* proj_b = (const float*)d_in[6];
    float* out = (float*)d_out;

    float *qkv, *qb, *kb, *attn;
    cudaGetSymbolAddress((void**)&qkv,  g_qkv);
    cudaGetSymbolAddress((void**)&qb,   g_q);
    cudaGetSymbolAddress((void**)&kb,   g_k);
    cudaGetSymbolAddress((void**)&attn, g_attn);

    // 1) QKV projection: [4096,1024] x [3072,1024]^T -> [4096,3072]
    gemm_nt<<<dim3(QKV_F / 128, ROWS / 128), 256>>>(x, qkv_w, nullptr, qkv,
                                                    ROWS, QKV_F, DIMC);
    // 2) RMSNorm + rotary (q scaled by D^-0.5)
    rms_rot_kernel<<<(2 * BQ * NHEAD * NSEQ) / 8, 256>>>(qkv, pos, qnw, knw, qb, kb);
    // 3) Flash attention
    attn_kernel<<<dim3(NSEQ / 128, NHEAD, BQ), 128>>>(qb, kb, qkv, attn);
    // 4) Output projection + bias: [4096,1024] x [1024,1024]^T -> out
    gemm_nt<<<dim3(DIMC / 128, ROWS / 128), 256>>>(attn, proj_w, proj_b, out,
                                                   ROWS, DIMC, DIMC);
}